// round 6
// baseline (speedup 1.0000x reference)
#include <cuda_runtime.h>
#include <cstdint>

// Problem constants
#define LEN_M   1088
#define MPRI    65
#define NSAMP   100        // M0 == M1 == 100
#define NROWS   16384
#define DD1     17         // DATA_DIM + 1
#define DH      64
#define OUT_PRED ((size_t)NROWS * NSAMP * NSAMP)   // 163,840,000

// Sampled weights (scratch, device globals — no allocation allowed)
__device__ float g_W0T[NSAMP * LEN_M];   // [m][j], j = d*64 + h
__device__ float g_w1[MPRI * NSAMP];     // [d][c]

// ---------------- Threefry2x32 (exact JAX rotation/key schedule) -------------
__host__ __device__ inline void threefry(uint32_t k0, uint32_t k1,
                                         uint32_t c0, uint32_t c1,
                                         uint32_t& o0, uint32_t& o1) {
    uint32_t ks2 = k0 ^ k1 ^ 0x1BD11BDAu;
    uint32_t x0 = c0 + k0, x1 = c1 + k1;
#define TF_ROUND(r) { x0 += x1; x1 = (x1 << (r)) | (x1 >> (32 - (r))); x1 ^= x0; }
    TF_ROUND(13) TF_ROUND(15) TF_ROUND(26) TF_ROUND(6)
    x0 += k1;  x1 += ks2 + 1u;
    TF_ROUND(17) TF_ROUND(29) TF_ROUND(16) TF_ROUND(24)
    x0 += ks2; x1 += k0 + 2u;
    TF_ROUND(13) TF_ROUND(15) TF_ROUND(26) TF_ROUND(6)
    x0 += k0;  x1 += k1 + 3u;
    TF_ROUND(17) TF_ROUND(29) TF_ROUND(16) TF_ROUND(24)
    x0 += k1;  x1 += ks2 + 4u;
    TF_ROUND(13) TF_ROUND(15) TF_ROUND(26) TF_ROUND(6)
    x0 += ks2; x1 += k0 + 5u;
#undef TF_ROUND
    o0 = x0; o1 = x1;
}

// XLA f32 ErfInv (Giles polynomial, exact coefficients)
__device__ inline float erfinv_xla(float x) {
    float w = -log1pf(-x * x);
    float p;
    if (w < 5.0f) {
        w -= 2.5f;
        p = 2.81022636e-08f;
        p = fmaf(p, w, 3.43273939e-07f);
        p = fmaf(p, w, -3.5233877e-06f);
        p = fmaf(p, w, -4.39150654e-06f);
        p = fmaf(p, w, 0.00021858087f);
        p = fmaf(p, w, -0.00125372503f);
        p = fmaf(p, w, -0.00417768164f);
        p = fmaf(p, w, 0.246640727f);
        p = fmaf(p, w, 1.50140941f);
    } else {
        w = sqrtf(w) - 3.0f;
        p = -0.000200214257f;
        p = fmaf(p, w, 0.000100950558f);
        p = fmaf(p, w, 0.00134934322f);
        p = fmaf(p, w, -0.00367342844f);
        p = fmaf(p, w, 0.00573950773f);
        p = fmaf(p, w, -0.0076224613f);
        p = fmaf(p, w, 0.00943887047f);
        p = fmaf(p, w, 1.00167406f);
        p = fmaf(p, w, 2.83297682f);
    }
    return p * x;
}

// JAX normal: u = uniform(nextafter(-1,0), 1) from top bits; sqrt(2)*erfinv(u)
__device__ inline float bits_to_normal(uint32_t bits) {
    float f = __uint_as_float((bits >> 9) | 0x3f800000u) - 1.0f;
    const float lo = -0.99999994f;            // nextafter(-1, 0) in f32
    float u = __fadd_rn(__fmul_rn(f, 2.0f), lo);  // (hi-lo) rounds to exactly 2.0f
    u = fmaxf(lo, u);
    return 1.4142135381698608f * erfinv_xla(u);
}

// ---------------- Kernel 1: sample weights + write output tail ---------------
// Partitionable threefry: element e draws from counter (hi=0, lo=e);
// for 32-bit width the two output words are XOR-FOLDED: bits = o0 ^ o1.
#define E0 108800  // eps0 elements: 1088*100
#define E1 6500    // eps1 elements: 65*100
#define TAILN 2306

__global__ void setup_kernel(const float* __restrict__ ms_vs,
                             float* __restrict__ out_tail,
                             uint32_t k0a, uint32_t k0b,
                             uint32_t k1a, uint32_t k1b) {
    int t = blockIdx.x * blockDim.x + threadIdx.x;
    if (t < E0) {
        uint32_t o0, o1;
        threefry(k0a, k0b, 0u, (uint32_t)t, o0, o1);
        float n = bits_to_normal(o0 ^ o1);
        // element e of eps0 (row-major 1088 x 100): j = e/100, m = e%100
        int j = t / 100, m = t - j * 100;
        float v = fabsf(ms_vs[1153 + j]) + 1e-6f;
        g_W0T[m * LEN_M + j] = fmaf(n, sqrtf(v), ms_vs[j]);
    } else if (t < E0 + E1) {
        int i = t - E0;
        uint32_t o0, o1;
        threefry(k1a, k1b, 0u, (uint32_t)i, o0, o1);
        float n = bits_to_normal(o0 ^ o1);
        int d = i / 100, c = i - d * 100;
        float v = fabsf(ms_vs[2241 + d]) + 1e-6f;
        g_w1[d * 100 + c] = fmaf(n, sqrtf(v), ms_vs[1088 + d]);
    } else if (t < E0 + E1 + TAILN) {
        int q = t - E0 - E1;
        float val;
        if (q < 1088)       val = ms_vs[q];                               // m_w0
        else if (q < 2176)  val = fabsf(ms_vs[1153 + (q - 1088)]) + 1e-6f; // v_w0
        else if (q < 2241)  val = ms_vs[1088 + (q - 2176)];               // m_pri
        else                val = fabsf(ms_vs[q]) + 1e-6f;                // v_pri
        out_tail[q] = val;
    }
}

// ---------------- Kernel 2: fused z = relu(x@W0_m), pred = [1,z]@w1 ----------
// One block: 128 n-rows x one sample m. 320 threads (10 warps).
// Phase 2: warp w owns cols [10w, 10w+10); lane owns rows {lane, lane+32, lane+64, lane+96}.
// Packed fp32x2 FMA (fma.rn.f32x2) doubles fp32 throughput on sm_103a.

#define TN 128
#define NT 320
#define SM_XS   0                 // 128*17  = 2176 floats
#define SM_W0   2176              // 17*64   = 1088
#define SM_W1   3264              // 65*100  = 6500
#define SM_ZS   9764              // 65*128  = 8320
#define SM_FLOATS 18084           // 72336 bytes

__global__ void __launch_bounds__(NT) pred_kernel(const float* __restrict__ x,
                                                  float* __restrict__ out) {
    extern __shared__ float sm[];
    float* XS  = sm + SM_XS;
    float* W0S = sm + SM_W0;
    float* W1S = sm + SM_W1;
    float* ZS  = sm + SM_ZS;

    const int tid = threadIdx.x;
    const int m   = blockIdx.y;
    const int n0  = blockIdx.x * TN;

    // ---- load tiles (all fully coalesced reads) ----
    for (int i = tid; i < TN * DD1; i += NT) XS[i]  = x[(size_t)n0 * DD1 + i];
    for (int i = tid; i < DD1 * DH; i += NT) W0S[i] = g_W0T[m * LEN_M + i]; // [k*64+h]
    for (int i = tid; i < MPRI * NSAMP; i += NT) W1S[i] = g_w1[i];
    for (int i = tid; i < TN; i += NT) ZS[i] = 1.0f;   // bias row d=0
    __syncthreads();

    // ---- phase 1: z[h+1][n] = relu(sum_k x[n][k] * W0[k][h]) ----
    for (int idx = tid; idx < TN * DH; idx += NT) {
        int n = idx & (TN - 1);
        int h = idx >> 7;
        float acc = 0.0f;
#pragma unroll
        for (int k = 0; k < DD1; ++k)
            acc = fmaf(XS[n * DD1 + k], W0S[k * DH + h], acc);
        ZS[(h + 1) * TN + n] = fmaxf(acc, 0.0f);
    }
    __syncthreads();

    // ---- phase 2: pred[n][c] = sum_d z[d][n] * w1[d][c], fp32x2 packed ----
    const int lane = tid & 31;
    const int wid  = tid >> 5;           // 0..9 -> col group
    unsigned long long acc[4][5];
#pragma unroll
    for (int i = 0; i < 4; ++i)
#pragma unroll
        for (int j = 0; j < 5; ++j) acc[i][j] = 0ull;

    for (int d = 0; d < MPRI; ++d) {
        unsigned long long zz[4];
#pragma unroll
        for (int i = 0; i < 4; ++i) {
            float z = ZS[d * TN + lane + 32 * i];
            asm("mov.b64 %0, {%1, %1};" : "=l"(zz[i]) : "f"(z));
        }
#pragma unroll
        for (int j = 0; j < 5; ++j) {
            unsigned long long w =
                *reinterpret_cast<const unsigned long long*>(W1S + d * NSAMP + wid * 10 + 2 * j);
#pragma unroll
            for (int i = 0; i < 4; ++i)
                asm("fma.rn.f32x2 %0, %1, %2, %3;"
                    : "=l"(acc[i][j]) : "l"(zz[i]), "l"(w), "l"(acc[i][j]));
        }
    }
    __syncthreads();   // everyone done reading ZS/W1S before overlay

    // ---- stage results in smem, then coalesced float4 global stores ----
    float* OS = sm;    // 128*100 = 12800 floats, overlays the tiles
#pragma unroll
    for (int i = 0; i < 4; ++i) {
        int r = lane + 32 * i;
#pragma unroll
        for (int j = 0; j < 5; ++j)
            *reinterpret_cast<unsigned long long*>(OS + r * NSAMP + wid * 10 + 2 * j) = acc[i][j];
    }
    __syncthreads();

    const size_t base = (size_t)n0 * (NSAMP * NSAMP) + (size_t)m * NSAMP;
    for (int idx = tid; idx < TN * NSAMP / 4; idx += NT) {
        int r = idx / 25;
        int q = idx - r * 25;
        float4 v = *reinterpret_cast<const float4*>(OS + r * NSAMP + 4 * q);
        *reinterpret_cast<float4*>(out + base + (size_t)r * (NSAMP * NSAMP) + 4 * q) = v;
    }
}

// ---------------------------------- launch -----------------------------------
extern "C" void kernel_launch(void* const* d_in, const int* in_sizes, int n_in,
                              void* d_out, int out_size) {
    const float* x;
    const float* ms_vs;
    if (in_sizes[0] == 2306) { ms_vs = (const float*)d_in[0]; x = (const float*)d_in[1]; }
    else                     { x = (const float*)d_in[0];     ms_vs = (const float*)d_in[1]; }
    float* out = (float*)d_out;

    // jax.random.key(42) == (0, 42). Partitionable (fold-like) split:
    // child key i = threefry(parent, (0, i)) -> both output words are the key.
    uint32_t k0a, k0b, k1a, k1b;
    threefry(0u, 42u, 0u, 0u, k0a, k0b);   // k0
    threefry(0u, 42u, 0u, 1u, k1a, k1b);   // k1

    setup_kernel<<<(E0 + E1 + TAILN + 255) / 256, 256>>>(ms_vs, out + OUT_PRED,
                                                         k0a, k0b, k1a, k1b);

    cudaFuncSetAttribute(pred_kernel, cudaFuncAttributeMaxDynamicSharedMemorySize,
                         SM_FLOATS * sizeof(float));
    pred_kernel<<<dim3(NROWS / TN, NSAMP), NT, SM_FLOATS * sizeof(float)>>>(x, out);
}

// round 7
// speedup vs baseline: 1.1487x; 1.1487x over previous
#include <cuda_runtime.h>
#include <cstdint>

// Problem constants
#define LEN_M   1088
#define MPRI    65
#define NSAMP   100
#define NROWS   16384
#define DD1     17
#define DH      64
#define OUT_PRED ((size_t)NROWS * NSAMP * NSAMP)   // 163,840,000

typedef unsigned long long u64;

// Sampled weights (scratch, device globals)
__device__ float g_W0T[NSAMP * LEN_M];        // [m][j], j = k*64 + h
__device__ float g_w1r[10 * MPRI * 12];       // [wid][d][12]: 10 cols padded to 12 (48B stride)

// ---------------- Threefry2x32 (exact JAX rotation/key schedule) -------------
__host__ __device__ inline void threefry(uint32_t k0, uint32_t k1,
                                         uint32_t c0, uint32_t c1,
                                         uint32_t& o0, uint32_t& o1) {
    uint32_t ks2 = k0 ^ k1 ^ 0x1BD11BDAu;
    uint32_t x0 = c0 + k0, x1 = c1 + k1;
#define TF_ROUND(r) { x0 += x1; x1 = (x1 << (r)) | (x1 >> (32 - (r))); x1 ^= x0; }
    TF_ROUND(13) TF_ROUND(15) TF_ROUND(26) TF_ROUND(6)
    x0 += k1;  x1 += ks2 + 1u;
    TF_ROUND(17) TF_ROUND(29) TF_ROUND(16) TF_ROUND(24)
    x0 += ks2; x1 += k0 + 2u;
    TF_ROUND(13) TF_ROUND(15) TF_ROUND(26) TF_ROUND(6)
    x0 += k0;  x1 += k1 + 3u;
    TF_ROUND(17) TF_ROUND(29) TF_ROUND(16) TF_ROUND(24)
    x0 += k1;  x1 += ks2 + 4u;
    TF_ROUND(13) TF_ROUND(15) TF_ROUND(26) TF_ROUND(6)
    x0 += ks2; x1 += k0 + 5u;
#undef TF_ROUND
    o0 = x0; o1 = x1;
}

// XLA f32 ErfInv (Giles polynomial, exact coefficients)
__device__ inline float erfinv_xla(float x) {
    float w = -log1pf(-x * x);
    float p;
    if (w < 5.0f) {
        w -= 2.5f;
        p = 2.81022636e-08f;
        p = fmaf(p, w, 3.43273939e-07f);
        p = fmaf(p, w, -3.5233877e-06f);
        p = fmaf(p, w, -4.39150654e-06f);
        p = fmaf(p, w, 0.00021858087f);
        p = fmaf(p, w, -0.00125372503f);
        p = fmaf(p, w, -0.00417768164f);
        p = fmaf(p, w, 0.246640727f);
        p = fmaf(p, w, 1.50140941f);
    } else {
        w = sqrtf(w) - 3.0f;
        p = -0.000200214257f;
        p = fmaf(p, w, 0.000100950558f);
        p = fmaf(p, w, 0.00134934322f);
        p = fmaf(p, w, -0.00367342844f);
        p = fmaf(p, w, 0.00573950773f);
        p = fmaf(p, w, -0.0076224613f);
        p = fmaf(p, w, 0.00943887047f);
        p = fmaf(p, w, 1.00167406f);
        p = fmaf(p, w, 2.83297682f);
    }
    return p * x;
}

__device__ inline float bits_to_normal(uint32_t bits) {
    float f = __uint_as_float((bits >> 9) | 0x3f800000u) - 1.0f;
    const float lo = -0.99999994f;
    float u = __fadd_rn(__fmul_rn(f, 2.0f), lo);
    u = fmaxf(lo, u);
    return 1.4142135381698608f * erfinv_xla(u);
}

// ---------------- Kernel 1: sample weights + write output tail ---------------
#define E0 108800  // eps0 elements: 1088*100
#define E1 6500    // eps1 elements: 65*100
#define TAILN 2306

__global__ void setup_kernel(const float* __restrict__ ms_vs,
                             float* __restrict__ out_tail,
                             uint32_t k0a, uint32_t k0b,
                             uint32_t k1a, uint32_t k1b) {
    int t = blockIdx.x * blockDim.x + threadIdx.x;
    if (t < E0) {
        uint32_t o0, o1;
        threefry(k0a, k0b, 0u, (uint32_t)t, o0, o1);
        float n = bits_to_normal(o0 ^ o1);
        int j = t / 100, m = t - j * 100;
        float v = fabsf(ms_vs[1153 + j]) + 1e-6f;
        g_W0T[m * LEN_M + j] = fmaf(n, sqrtf(v), ms_vs[j]);
    } else if (t < E0 + E1) {
        int i = t - E0;
        uint32_t o0, o1;
        threefry(k1a, k1b, 0u, (uint32_t)i, o0, o1);
        float n = bits_to_normal(o0 ^ o1);
        int d = i / 100, c = i - d * 100;
        float v = fabsf(ms_vs[2241 + d]) + 1e-6f;
        float val = fmaf(n, sqrtf(v), ms_vs[1088 + d]);
        int wid = c / 10, cc = c - wid * 10;
        g_w1r[(wid * MPRI + d) * 12 + cc] = val;
    } else if (t < E0 + E1 + TAILN) {
        int q = t - E0 - E1;
        float val;
        if (q < 1088)       val = ms_vs[q];
        else if (q < 2176)  val = fabsf(ms_vs[1153 + (q - 1088)]) + 1e-6f;
        else if (q < 2241)  val = ms_vs[1088 + (q - 2176)];
        else                val = fabsf(ms_vs[q]) + 1e-6f;
        out_tail[q] = val;
    }
}

// ---------------- Kernel 2: fused z = relu(x@W0_m), pred = [1,z]@w1 ----------
// Block: 128 rows x one sample m, 320 threads.
// Phase 1 (256 threads): x row in regs, W0 broadcast LDS.128 h-quads, f32x2.
// Phase 2: warp wid owns cols [10*wid,+10); lane owns rows lane+{0,32,64,96}.
//          w via broadcast LDG.128/LDG.64 from g_w1r (L1-resident, 31KB hot).
// Staging: OS row stride 102 -> conflict-free STS.64 / LDS.64.

#define TN 128
#define NT 320
#define OSS 102                          // OS row stride (floats)
#define SM_FLOATS (TN * OSS)             // 13056 floats = 52224 B (covers tiles too)

__global__ void __launch_bounds__(NT, 3) pred_kernel(const float* __restrict__ x,
                                                     float* __restrict__ out) {
    extern __shared__ float sm[];
    float* XS  = sm;            // 2176
    float* W0S = sm + 2176;     // 1088
    float* ZS  = sm + 3264;     // 65*128 = 8320 (row 0 = bias)

    const int tid  = threadIdx.x;
    const int lane = tid & 31;
    const int wid  = tid >> 5;
    const int m    = blockIdx.y;
    const int n0   = blockIdx.x * TN;

    // ---- fills (all float4, coalesced) ----
    {
        const float4* xg = reinterpret_cast<const float4*>(x + (size_t)n0 * DD1);
        for (int i = tid; i < TN * DD1 / 4; i += NT)
            reinterpret_cast<float4*>(XS)[i] = xg[i];
        const float4* wg = reinterpret_cast<const float4*>(g_W0T + m * LEN_M);
        for (int i = tid; i < DD1 * DH / 4; i += NT)
            reinterpret_cast<float4*>(W0S)[i] = wg[i];
        for (int i = tid; i < TN; i += NT) ZS[i] = 1.0f;
    }
    __syncthreads();

    // ---- phase 1: threads 0..255; thread = (row n, h-half) ----
    if (tid < 256) {
        const int n  = tid & 127;
        const int hh = tid >> 7;                 // 0 or 1
        float xr[DD1];
#pragma unroll
        for (int k = 0; k < DD1; ++k) xr[k] = XS[n * DD1 + k];
#pragma unroll
        for (int q = 0; q < 8; ++q) {
            const int h = hh * 32 + q * 4;
            u64 a0 = 0ull, a1 = 0ull;
#pragma unroll
            for (int k = 0; k < DD1; ++k) {
                // broadcast quad of W0[k][h..h+3] (uniform addr across warp)
                const u64* wq = reinterpret_cast<const u64*>(W0S + k * DH + h);
                u64 w01 = wq[0], w23 = wq[1];
                u64 xx;
                asm("mov.b64 %0, {%1, %1};" : "=l"(xx) : "f"(xr[k]));
                asm("fma.rn.f32x2 %0, %1, %2, %3;" : "=l"(a0) : "l"(xx), "l"(w01), "l"(a0));
                asm("fma.rn.f32x2 %0, %1, %2, %3;" : "=l"(a1) : "l"(xx), "l"(w23), "l"(a1));
            }
            float r0, r1, r2, r3;
            asm("mov.b64 {%0, %1}, %2;" : "=f"(r0), "=f"(r1) : "l"(a0));
            asm("mov.b64 {%0, %1}, %2;" : "=f"(r2), "=f"(r3) : "l"(a1));
            ZS[(h + 1) * TN + n] = fmaxf(r0, 0.0f);
            ZS[(h + 2) * TN + n] = fmaxf(r1, 0.0f);
            ZS[(h + 3) * TN + n] = fmaxf(r2, 0.0f);
            ZS[(h + 4) * TN + n] = fmaxf(r3, 0.0f);
        }
    }
    __syncthreads();

    // ---- phase 2 ----
    const float* wp = g_w1r + wid * (MPRI * 12);
    u64 acc[4][5];
#pragma unroll
    for (int i = 0; i < 4; ++i)
#pragma unroll
        for (int j = 0; j < 5; ++j) acc[i][j] = 0ull;

    for (int d = 0; d < MPRI; ++d) {
        // 10 cols as 2x LDG.128 + 1x LDG.64 broadcast (16B-aligned, L1 hot)
        const ulonglong2 wa = *reinterpret_cast<const ulonglong2*>(wp + d * 12);
        const ulonglong2 wb = *reinterpret_cast<const ulonglong2*>(wp + d * 12 + 4);
        const u64        wc = *reinterpret_cast<const u64*>(wp + d * 12 + 8);
        u64 zz[4];
#pragma unroll
        for (int i = 0; i < 4; ++i) {
            float z = ZS[d * TN + lane + 32 * i];
            asm("mov.b64 %0, {%1, %1};" : "=l"(zz[i]) : "f"(z));
        }
#pragma unroll
        for (int i = 0; i < 4; ++i) {
            asm("fma.rn.f32x2 %0, %1, %2, %3;" : "=l"(acc[i][0]) : "l"(zz[i]), "l"(wa.x), "l"(acc[i][0]));
            asm("fma.rn.f32x2 %0, %1, %2, %3;" : "=l"(acc[i][1]) : "l"(zz[i]), "l"(wa.y), "l"(acc[i][1]));
            asm("fma.rn.f32x2 %0, %1, %2, %3;" : "=l"(acc[i][2]) : "l"(zz[i]), "l"(wb.x), "l"(acc[i][2]));
            asm("fma.rn.f32x2 %0, %1, %2, %3;" : "=l"(acc[i][3]) : "l"(zz[i]), "l"(wb.y), "l"(acc[i][3]));
            asm("fma.rn.f32x2 %0, %1, %2, %3;" : "=l"(acc[i][4]) : "l"(zz[i]), "l"(wc),   "l"(acc[i][4]));
        }
    }
    __syncthreads();   // done reading ZS before overlay

    // ---- stage in smem (stride 102: conflict-free u64), then coalesced STG ----
    float* OS = sm;
#pragma unroll
    for (int i = 0; i < 4; ++i) {
        int r = lane + 32 * i;
#pragma unroll
        for (int j = 0; j < 5; ++j)
            *reinterpret_cast<u64*>(OS + r * OSS + wid * 10 + 2 * j) = acc[i][j];
    }
    __syncthreads();

    const size_t base = (size_t)n0 * (NSAMP * NSAMP) + (size_t)m * NSAMP;
    for (int idx = tid; idx < TN * NSAMP / 2; idx += NT) {
        int r = idx / 50;
        int q = idx - r * 50;
        u64 v = *reinterpret_cast<const u64*>(OS + r * OSS + 2 * q);
        *reinterpret_cast<u64*>(out + base + (size_t)r * (NSAMP * NSAMP) + 2 * q) = v;
    }
}

// ---------------------------------- launch -----------------------------------
extern "C" void kernel_launch(void* const* d_in, const int* in_sizes, int n_in,
                              void* d_out, int out_size) {
    const float* x;
    const float* ms_vs;
    if (in_sizes[0] == 2306) { ms_vs = (const float*)d_in[0]; x = (const float*)d_in[1]; }
    else                     { x = (const float*)d_in[0];     ms_vs = (const float*)d_in[1]; }
    float* out = (float*)d_out;

    // jax.random.key(42) == (0, 42); fold-like split: child i = threefry(parent,(0,i))
    uint32_t k0a, k0b, k1a, k1b;
    threefry(0u, 42u, 0u, 0u, k0a, k0b);
    threefry(0u, 42u, 0u, 1u, k1a, k1b);

    setup_kernel<<<(E0 + E1 + TAILN + 255) / 256, 256>>>(ms_vs, out + OUT_PRED,
                                                         k0a, k0b, k1a, k1b);

    cudaFuncSetAttribute(pred_kernel, cudaFuncAttributeMaxDynamicSharedMemorySize,
                         SM_FLOATS * sizeof(float));
    pred_kernel<<<dim3(NROWS / TN, NSAMP), NT, SM_FLOATS * sizeof(float)>>>(x, out);
}

// round 9
// speedup vs baseline: 2.7276x; 2.3744x over previous
#include <cuda_runtime.h>
#include <cstdint>

// Problem constants
#define LEN_M   1088
#define MPRI    65
#define NSAMP   100
#define NROWS   16384
#define DD1     17
#define DH      64
#define OUT_PRED ((size_t)NROWS * NSAMP * NSAMP)

typedef unsigned long long u64;
typedef uint32_t u32;

// ---------------- device globals (scratch; no allocation allowed) ------------
__device__ float g_W0T[NSAMP * LEN_M];            // [m][j], j=k*64+h  (fp32)
__device__ float g_w1[MPRI * NSAMP];              // [d][c]            (fp32)
// bf16 hi/lo operand images (ldmatrix-friendly padded rows, 16B aligned):
__device__ uint4 g_ximgH[NROWS * 5];              // [n][40 bf16] K=17 pad 32
__device__ uint4 g_ximgL[NROWS * 5];
__device__ uint4 g_w0imgH[NSAMP * 320];           // per m: [64 h][40 bf16]
__device__ uint4 g_w0imgL[NSAMP * 320];
__device__ uint4 g_w1imgH[936];                   // [104 c][72 bf16] K=64 (d=1..64)
__device__ uint4 g_w1imgL[936];

// ---------------- Threefry2x32 (exact JAX rotation/key schedule) -------------
__host__ __device__ inline void threefry(u32 k0, u32 k1, u32 c0, u32 c1,
                                         u32& o0, u32& o1) {
    u32 ks2 = k0 ^ k1 ^ 0x1BD11BDAu;
    u32 x0 = c0 + k0, x1 = c1 + k1;
#define TF_ROUND(r) { x0 += x1; x1 = (x1 << (r)) | (x1 >> (32 - (r))); x1 ^= x0; }
    TF_ROUND(13) TF_ROUND(15) TF_ROUND(26) TF_ROUND(6)
    x0 += k1;  x1 += ks2 + 1u;
    TF_ROUND(17) TF_ROUND(29) TF_ROUND(16) TF_ROUND(24)
    x0 += ks2; x1 += k0 + 2u;
    TF_ROUND(13) TF_ROUND(15) TF_ROUND(26) TF_ROUND(6)
    x0 += k0;  x1 += k1 + 3u;
    TF_ROUND(17) TF_ROUND(29) TF_ROUND(16) TF_ROUND(24)
    x0 += k1;  x1 += ks2 + 4u;
    TF_ROUND(13) TF_ROUND(15) TF_ROUND(26) TF_ROUND(6)
    x0 += ks2; x1 += k0 + 5u;
#undef TF_ROUND
    o0 = x0; o1 = x1;
}

__device__ inline float erfinv_xla(float x) {
    float w = -log1pf(-x * x);
    float p;
    if (w < 5.0f) {
        w -= 2.5f;
        p = 2.81022636e-08f;
        p = fmaf(p, w, 3.43273939e-07f);
        p = fmaf(p, w, -3.5233877e-06f);
        p = fmaf(p, w, -4.39150654e-06f);
        p = fmaf(p, w, 0.00021858087f);
        p = fmaf(p, w, -0.00125372503f);
        p = fmaf(p, w, -0.00417768164f);
        p = fmaf(p, w, 0.246640727f);
        p = fmaf(p, w, 1.50140941f);
    } else {
        w = sqrtf(w) - 3.0f;
        p = -0.000200214257f;
        p = fmaf(p, w, 0.000100950558f);
        p = fmaf(p, w, 0.00134934322f);
        p = fmaf(p, w, -0.00367342844f);
        p = fmaf(p, w, 0.00573950773f);
        p = fmaf(p, w, -0.0076224613f);
        p = fmaf(p, w, 0.00943887047f);
        p = fmaf(p, w, 1.00167406f);
        p = fmaf(p, w, 2.83297682f);
    }
    return p * x;
}

__device__ inline float bits_to_normal(u32 bits) {
    float f = __uint_as_float((bits >> 9) | 0x3f800000u) - 1.0f;
    const float lo = -0.99999994f;
    float u = __fadd_rn(__fmul_rn(f, 2.0f), lo);
    u = fmaxf(lo, u);
    return 1.4142135381698608f * erfinv_xla(u);
}

// ---------------- setup1: sample weights (fp32) + output tail ----------------
#define E0 108800
#define E1 6500
#define TAILN 2306

__global__ void setup1_kernel(const float* __restrict__ ms_vs,
                              float* __restrict__ out_tail,
                              u32 k0a, u32 k0b, u32 k1a, u32 k1b) {
    int t = blockIdx.x * blockDim.x + threadIdx.x;
    if (t < E0) {
        u32 o0, o1;
        threefry(k0a, k0b, 0u, (u32)t, o0, o1);
        float n = bits_to_normal(o0 ^ o1);
        int j = t / 100, m = t - j * 100;
        float v = fabsf(ms_vs[1153 + j]) + 1e-6f;
        g_W0T[m * LEN_M + j] = fmaf(n, sqrtf(v), ms_vs[j]);
    } else if (t < E0 + E1) {
        int i = t - E0;
        u32 o0, o1;
        threefry(k1a, k1b, 0u, (u32)i, o0, o1);
        float n = bits_to_normal(o0 ^ o1);
        int d = i / 100, c = i - d * 100;
        float v = fabsf(ms_vs[2241 + d]) + 1e-6f;
        g_w1[d * 100 + c] = fmaf(n, sqrtf(v), ms_vs[1088 + d]);
    } else if (t < E0 + E1 + TAILN) {
        int q = t - E0 - E1;
        float val;
        if (q < 1088)       val = ms_vs[q];
        else if (q < 2176)  val = fabsf(ms_vs[1153 + (q - 1088)]) + 1e-6f;
        else if (q < 2241)  val = ms_vs[1088 + (q - 2176)];
        else                val = fabsf(ms_vs[q]) + 1e-6f;
        out_tail[q] = val;
    }
}

// ---------------- setup2: build bf16 hi/lo operand images --------------------
__device__ inline void bf16split2(float a, float b, u32& H, u32& L) {
    asm("cvt.rn.bf16x2.f32 %0, %1, %2;" : "=r"(H) : "f"(b), "f"(a));  // lo half = a
    float hf0 = __uint_as_float(H << 16);
    float hf1 = __uint_as_float(H & 0xFFFF0000u);
    float l0 = a - hf0, l1 = b - hf1;
    asm("cvt.rn.bf16x2.f32 %0, %1, %2;" : "=r"(L) : "f"(l1), "f"(l0));
}

#define SX2 (NROWS * 20)        // X image u32 slots
#define SW0 (NSAMP * 64 * 20)   // 128000
#define SW1 (104 * 36)          // 3744

__global__ void setup2_kernel(const float* __restrict__ x) {
    int s = blockIdx.x * blockDim.x + threadIdx.x;
    if (s < SX2) {
        int n = s / 20, p = s - n * 20;
        int k = 2 * p;
        float a = (k     < DD1) ? x[n * DD1 + k]     : 0.0f;
        float b = (k + 1 < DD1) ? x[n * DD1 + k + 1] : 0.0f;
        u32 H, L; bf16split2(a, b, H, L);
        ((u32*)g_ximgH)[s] = H;
        ((u32*)g_ximgL)[s] = L;
    } else if (s < SX2 + SW0) {
        int r = s - SX2;
        int m = r / 1280, t = r - m * 1280;
        int h = t / 20, p = t - h * 20;
        int k = 2 * p;
        float a = (k     < DD1) ? g_W0T[m * LEN_M + k * DH + h]       : 0.0f;
        float b = (k + 1 < DD1) ? g_W0T[m * LEN_M + (k + 1) * DH + h] : 0.0f;
        u32 H, L; bf16split2(a, b, H, L);
        ((u32*)g_w0imgH)[r] = H;
        ((u32*)g_w0imgL)[r] = L;
    } else if (s < SX2 + SW0 + SW1) {
        int r = s - SX2 - SW0;
        int c = r / 36, p = r - c * 36;
        int k = 2 * p;                            // K idx -> w1 row d=k+1
        float a = (k     < 64 && c < 100) ? g_w1[(k + 1) * 100 + c] : 0.0f;
        float b = (k + 1 < 64 && c < 100) ? g_w1[(k + 2) * 100 + c] : 0.0f;
        u32 H, L; bf16split2(a, b, H, L);
        ((u32*)g_w1imgH)[r] = H;
        ((u32*)g_w1imgL)[r] = L;
    }
}

// ---------------- mma.sync / ldmatrix helpers --------------------------------
__device__ __forceinline__ void ldx4(u32* r, u32 addr) {
    asm volatile("ldmatrix.sync.aligned.m8n8.x4.shared.b16 {%0,%1,%2,%3}, [%4];"
                 : "=r"(r[0]), "=r"(r[1]), "=r"(r[2]), "=r"(r[3]) : "r"(addr));
}
__device__ __forceinline__ void ldx2(u32* r, u32 addr) {
    asm volatile("ldmatrix.sync.aligned.m8n8.x2.shared.b16 {%0,%1}, [%2];"
                 : "=r"(r[0]), "=r"(r[1]) : "r"(addr));
}
__device__ __forceinline__ void mma16816(float* d, const u32* a, const u32* b) {
    asm volatile("mma.sync.aligned.m16n8k16.row.col.f32.bf16.bf16.f32 "
                 "{%0,%1,%2,%3}, {%4,%5,%6,%7}, {%8,%9}, {%0,%1,%2,%3};"
                 : "+f"(d[0]), "+f"(d[1]), "+f"(d[2]), "+f"(d[3])
                 : "r"(a[0]), "r"(a[1]), "r"(a[2]), "r"(a[3]), "r"(b[0]), "r"(b[1]));
}
#define MBAR_INIT(a, n)   asm volatile("mbarrier.init.shared.b64 [%0], %1;" :: "r"(a), "r"((u32)(n)) : "memory")
#define MBAR_EXPECT(a, b) asm volatile("mbarrier.arrive.expect_tx.shared.b64 _, [%0], %1;" :: "r"(a), "r"((u32)(b)) : "memory")
__device__ __forceinline__ void mbar_wait(u32 addr, u32 parity) {
    asm volatile("{\n\t.reg .pred P1;\n\t"
        "WAIT_LOOP_%=:\n\t"
        "mbarrier.try_wait.parity.acquire.cta.shared::cta.b64 P1, [%0], %1, 0x989680;\n\t"
        "@P1 bra.uni WAIT_DONE_%=;\n\t"
        "bra.uni WAIT_LOOP_%=;\n\t"
        "WAIT_DONE_%=:\n\t}"
        :: "r"(addr), "r"(parity) : "memory");
}
__device__ __forceinline__ void bulk_cp(u32 dst_smem, const void* src, u32 bytes, u32 mbar) {
    asm volatile("cp.async.bulk.shared::cluster.global.mbarrier::complete_tx::bytes "
                 "[%0], [%1], %2, [%3];"
                 :: "r"(dst_smem), "l"(src), "r"(bytes), "r"(mbar) : "memory");
}

// ---------------- pred kernel ------------------------------------------------
// smem (bytes): Xh/Xl [128][80B], W0h/l [64][80B], W1h/l [104][144B], Zh/l [128][144B]
#define SM_XH   1024
#define SM_XL   11264
#define SM_W0H  21504
#define SM_W0L  26624
#define SM_W1H  31744
#define SM_W1L  46720
#define SM_ZH   61696
#define SM_ZL   80128
#define SM_BYTES 98560
#define FILL_BYTES 60672u

__global__ void __launch_bounds__(256, 2) pred_kernel(float* __restrict__ out) {
    extern __shared__ char sm[];
    u32 sb;
    asm("{ .reg .u64 t; cvta.to.shared.u64 t, %1; cvt.u32.u64 %0, t; }"
        : "=r"(sb) : "l"(sm));

    const int tid  = threadIdx.x;
    const int lane = tid & 31;
    const int w    = tid >> 5;              // 0..7: n-strip rows 16w..16w+15
    const int m    = blockIdx.y;
    const int n0   = blockIdx.x * 128;

    if (tid == 0) {
        MBAR_INIT(sb + 8, 1);
        MBAR_EXPECT(sb + 8, FILL_BYTES);
        bulk_cp(sb + SM_XH,  g_ximgH  + (size_t)n0 * 5,  10240u, sb + 8);
        bulk_cp(sb + SM_XL,  g_ximgL  + (size_t)n0 * 5,  10240u, sb + 8);
        bulk_cp(sb + SM_W0H, g_w0imgH + (size_t)m * 320,  5120u, sb + 8);
        bulk_cp(sb + SM_W0L, g_w0imgL + (size_t)m * 320,  5120u, sb + 8);
        bulk_cp(sb + SM_W1H, g_w1imgH, 14976u, sb + 8);
        bulk_cp(sb + SM_W1L, g_w1imgL, 14976u, sb + 8);
    }
    __syncthreads();
    mbar_wait(sb + 8, 0);

    // ---- GEMM1: D1[16 rows x 64 h] per warp; K=32 (padded), 3-product split --
    float acc1[8][4];
#pragma unroll
    for (int t = 0; t < 8; ++t)
#pragma unroll
        for (int j = 0; j < 4; ++j) acc1[t][j] = 0.0f;

    {
        const u32 aH = sb + SM_XH + (16 * w + (lane & 15)) * 80 + (lane >> 4) * 16;
        const u32 aL = sb + SM_XL + (16 * w + (lane & 15)) * 80 + (lane >> 4) * 16;
        const u32 bB = (lane & 7) * 80 + ((lane >> 3) & 1) * 16;
#pragma unroll
        for (int ks = 0; ks < 2; ++ks) {
            u32 Ah[4], Al[4];
            ldx4(Ah, aH + ks * 32);
            ldx4(Al, aL + ks * 32);
#pragma unroll
            for (int t = 0; t < 8; ++t) {
                u32 Bh[2], Bl[2];
                ldx2(Bh, sb + SM_W0H + t * 640 + bB + ks * 32);
                ldx2(Bl, sb + SM_W0L + t * 640 + bB + ks * 32);
                mma16816(acc1[t], Ah, Bh);
                mma16816(acc1[t], Ah, Bl);
                mma16816(acc1[t], Al, Bh);
            }
        }
    }

    // ---- epi1: relu + bf16 split -> Zh/Zl smem ([128][144B]) ----
    {
        const int r0 = 16 * w + (lane >> 2);
        const int cb = 2 * (lane & 3);
#pragma unroll
        for (int t = 0; t < 8; ++t) {
            u32 H, L;
            float z0 = fmaxf(acc1[t][0], 0.0f), z1 = fmaxf(acc1[t][1], 0.0f);
            bf16split2(z0, z1, H, L);
            u32 off = r0 * 144 + (8 * t + cb) * 2;
            *(u32*)(sm + SM_ZH + off) = H;
            *(u32*)(sm + SM_ZL + off) = L;
            float z2 = fmaxf(acc1[t][2], 0.0f), z3 = fmaxf(acc1[t][3], 0.0f);
            bf16split2(z2, z3, H, L);
            off += 8 * 144;
            *(u32*)(sm + SM_ZH + off) = H;
            *(u32*)(sm + SM_ZL + off) = L;
        }
    }
    __syncthreads();

    // ---- GEMM2: D2[16 rows x 104 c] per warp; K=64; bias preloaded ----
    float acc[13][4];
    {
        const int cb = 2 * (lane & 3);
#pragma unroll
        for (int t = 0; t < 13; ++t) {
            int c = 8 * t + cb;
            float b0 = (c     < 100) ? g_w1[c]     : 0.0f;
            float b1 = (c + 1 < 100) ? g_w1[c + 1] : 0.0f;
            acc[t][0] = b0; acc[t][1] = b1; acc[t][2] = b0; acc[t][3] = b1;
        }
    }
    {
        const u32 aH = sb + SM_ZH + (16 * w + (lane & 15)) * 144 + (lane >> 4) * 16;
        const u32 aL = sb + SM_ZL + (16 * w + (lane & 15)) * 144 + (lane >> 4) * 16;
        const u32 bB = (lane & 7) * 144 + ((lane >> 3) & 1) * 16;
#pragma unroll
        for (int ks = 0; ks < 4; ++ks) {
            u32 Ah[4], Al[4];
            ldx4(Ah, aH + ks * 32);
            ldx4(Al, aL + ks * 32);
#pragma unroll
            for (int t = 0; t < 13; ++t) {
                u32 Bh[2], Bl[2];
                ldx2(Bh, sb + SM_W1H + t * 1152 + bB + ks * 32);
                ldx2(Bl, sb + SM_W1L + t * 1152 + bB + ks * 32);
                mma16816(acc[t], Ah, Bh);
                mma16816(acc[t], Ah, Bl);
                mma16816(acc[t], Al, Bh);
            }
        }
    }

    // ---- epi2: direct float2 STG from accumulators ----
    {
        const int cb = 2 * (lane & 3);
        const size_t rb = (size_t)(n0 + 16 * w + (lane >> 2)) * 10000 + (size_t)m * 100;
#pragma unroll
        for (int t = 0; t < 13; ++t) {
            int c = 8 * t + cb;
            if (c < 100) {
                *(float2*)(out + rb + c)         = make_float2(acc[t][0], acc[t][1]);
                *(float2*)(out + rb + 80000 + c) = make_float2(acc[t][2], acc[t][3]);
            }
        }
    }
}

// ---------------------------------- launch -----------------------------------
extern "C" void kernel_launch(void* const* d_in, const int* in_sizes, int n_in,
                              void* d_out, int out_size) {
    const float* x;
    const float* ms_vs;
    if (in_sizes[0] == 2306) { ms_vs = (const float*)d_in[0]; x = (const float*)d_in[1]; }
    else                     { x = (const float*)d_in[0];     ms_vs = (const float*)d_in[1]; }
    float* out = (float*)d_out;

    u32 k0a, k0b, k1a, k1b;
    threefry(0u, 42u, 0u, 0u, k0a, k0b);
    threefry(0u, 42u, 0u, 1u, k1a, k1b);

    setup1_kernel<<<(E0 + E1 + TAILN + 255) / 256, 256>>>(ms_vs, out + OUT_PRED,
                                                          k0a, k0b, k1a, k1b);
    setup2_kernel<<<(SX2 + SW0 + SW1 + 255) / 256, 256>>>(x);

    cudaFuncSetAttribute(pred_kernel, cudaFuncAttributeMaxDynamicSharedMemorySize, SM_BYTES);
    pred_kernel<<<dim3(NROWS / 128, NSAMP), 256, SM_BYTES>>>(out);
}